// round 12
// baseline (speedup 1.0000x reference)
#include <cuda_runtime.h>
#include <cuda_bf16.h>
#include <cstdint>
#include <cstddef>

// ===================== problem constants =====================
#define N_ROIS   128
#define N_CH     512
#define FH       37
#define FW       37
#define K_FC6    25088      // 512*7*7
#define NFC      4096
#define KSPLIT   4
#define MT       2          // M tiles (64 rows each)

// ===================== static scratch =====================
__device__ __align__(256) float g_pooled[N_ROIS * K_FC6];
__device__ __align__(256) float g_fc6[N_ROIS * NFC];
__device__ __align__(256) float g_fc7[N_ROIS * NFC];
__device__ __align__(256) float g_part[KSPLIT * N_ROIS * NFC];

// ===================== helpers =====================
__device__ __forceinline__ uint32_t smem_u32(const void* p) {
    uint32_t a;
    asm("{ .reg .u64 t; cvta.to.shared.u64 t, %1; cvt.u32.u64 %0, t; }" : "=r"(a) : "l"(p));
    return a;
}

__device__ __forceinline__ void split2_pair(float a, float b, uint32_t& h, uint32_t& l) {
    __nv_bfloat16 ha = __float2bfloat16_rn(a), hb = __float2bfloat16_rn(b);
    __nv_bfloat16 la = __float2bfloat16_rn(a - __bfloat162float(ha));
    __nv_bfloat16 lb = __float2bfloat16_rn(b - __bfloat162float(hb));
    h = (uint32_t)__bfloat16_as_ushort(ha) | ((uint32_t)__bfloat16_as_ushort(hb) << 16);
    l = (uint32_t)__bfloat16_as_ushort(la) | ((uint32_t)__bfloat16_as_ushort(lb) << 16);
}

__device__ __forceinline__ void mma16816(float* d, const uint32_t* a, const uint32_t* b) {
    asm volatile(
        "mma.sync.aligned.m16n8k16.row.col.f32.bf16.bf16.f32 "
        "{%0,%1,%2,%3}, {%4,%5,%6,%7}, {%8,%9}, {%0,%1,%2,%3};"
        : "+f"(d[0]), "+f"(d[1]), "+f"(d[2]), "+f"(d[3])
        : "r"(a[0]), "r"(a[1]), "r"(a[2]), "r"(a[3]), "r"(b[0]), "r"(b[1]));
}

#define LDSM4(R, ADDR) \
    asm volatile("ldmatrix.sync.aligned.m8n8.x4.shared.b16 {%0,%1,%2,%3}, [%4];" \
        : "=r"((R)[0]), "=r"((R)[1]), "=r"((R)[2]), "=r"((R)[3]) : "r"(ADDR))

__device__ __forceinline__ void cp16(uint32_t saddr, const void* g) {
    asm volatile("cp.async.cg.shared.global [%0], [%1], 16;" :: "r"(saddr), "l"(g) : "memory");
}
#define CP_COMMIT() asm volatile("cp.async.commit_group;" ::: "memory")
#define CP_WAIT1()  asm volatile("cp.async.wait_group 1;" ::: "memory")

// ===================== GEMM: M64 x N128 tile, 256 thr, 2 CTAs/SM, cp.async pipeline =====================
// Per iter: cp.async(stage s+2) -> compute(stage s) -> wait_group 1 -> convert(stage s+1) -> bar.
// smem: bf16-plane ring B[2] (30720 B each: A_H|A_L|B_H|B_L, 80B rows) + fp32 ring F[2] (24576 B each).
__global__ __launch_bounds__(256, 2)
void gemm_pipe(const float* __restrict__ A, const float* __restrict__ B,
               float* __restrict__ P, int K, int Kchunk, int Ntot, int n_tiles)
{
    extern __shared__ uint32_t sm[];
    constexpr int BM = 64, BN = 128, NTW = 4;
    constexpr uint32_t BSTG = 30720, FSTG = 24576;
    constexpr uint32_t F_OFF = 2 * BSTG;            // 61440 B
    constexpr uint32_t A_H32 = 0, A_L32 = 1280, B_H32 = 2560, B_L32 = 5120; // b32 offsets in B stage

    const int t = threadIdx.x;
    const int wid = t >> 5, lid = t & 31;
    const int wm = wid & 1, wn = wid >> 1;          // 2 x 4 warp grid
    const int ntile = blockIdx.x % n_tiles;
    const int mk = blockIdx.x / n_tiles;
    const int mtile = mk % MT;
    const int ksp = mk / MT;
    const int k_begin = ksp * Kchunk;
    const int S = Kchunk >> 5;

    const float* At = A + (size_t)(mtile * BM) * K;
    const float* Bt = B + (size_t)(ntile * BN) * K;
    const int ar = t >> 2, ac = t & 3;              // convert-A: row, 8-float group
    const int br = t >> 1, bc = t & 1;              // convert-B: row, 16-float group

    const int aRow = lid & 15;
    const int aK8 = (lid >> 4) & 1;
    const int bRow = (lid & 7) | ((lid & 16) >> 1);
    const int bK8 = (lid >> 3) & 1;

    const uint32_t sb = smem_u32(sm);
    char* smc = reinterpret_cast<char*>(sm);

    float acc[2][NTW][4];
#pragma unroll
    for (int i = 0; i < 2; ++i)
#pragma unroll
        for (int j = 0; j < NTW; ++j)
#pragma unroll
            for (int q = 0; q < 4; ++q) acc[i][j][q] = 0.0f;

    auto load_f = [&](int k0, int fb) {
        const uint32_t fbase = sb + F_OFF + (uint32_t)fb * FSTG;
        // A tile: 64 rows x 128 B = 512 x 16B chunks
#pragma unroll
        for (int j = 0; j < 2; ++j) {
            int id = t + j * 256;
            cp16(fbase + (id >> 3) * 128 + (id & 7) * 16,
                 At + (size_t)(id >> 3) * K + k0 + (id & 7) * 4);
        }
        // B tile: 128 rows x 128 B = 1024 chunks
#pragma unroll
        for (int j = 0; j < 4; ++j) {
            int id = t + j * 256;
            cp16(fbase + 8192 + (id >> 3) * 128 + (id & 7) * 16,
                 Bt + (size_t)(id >> 3) * K + k0 + (id & 7) * 4);
        }
    };

    auto convert = [&](int fb, int bb) {
        const char* f = smc + F_OFF + (uint32_t)fb * FSTG;
        uint32_t* bs = sm + (uint32_t)bb * (BSTG / 4);
        {   // A: 8 floats -> hi/lo uint4
            const float4 u0 = *reinterpret_cast<const float4*>(f + ar * 128 + ac * 32);
            const float4 u1 = *reinterpret_cast<const float4*>(f + ar * 128 + ac * 32 + 16);
            float ff[8] = {u0.x, u0.y, u0.z, u0.w, u1.x, u1.y, u1.z, u1.w};
            uint32_t hv[4], lv[4];
#pragma unroll
            for (int j = 0; j < 4; ++j) split2_pair(ff[2 * j], ff[2 * j + 1], hv[j], lv[j]);
            const int o = ar * 20 + ac * 4;
            *reinterpret_cast<uint4*>(bs + A_H32 + o) = make_uint4(hv[0], hv[1], hv[2], hv[3]);
            *reinterpret_cast<uint4*>(bs + A_L32 + o) = make_uint4(lv[0], lv[1], lv[2], lv[3]);
        }
        {   // B: 16 floats -> 2x hi/lo uint4
            const char* fB = f + 8192;
            const float4 v0 = *reinterpret_cast<const float4*>(fB + br * 128 + bc * 64);
            const float4 v1 = *reinterpret_cast<const float4*>(fB + br * 128 + bc * 64 + 16);
            const float4 v2 = *reinterpret_cast<const float4*>(fB + br * 128 + bc * 64 + 32);
            const float4 v3 = *reinterpret_cast<const float4*>(fB + br * 128 + bc * 64 + 48);
            float ff[16] = {v0.x, v0.y, v0.z, v0.w, v1.x, v1.y, v1.z, v1.w,
                            v2.x, v2.y, v2.z, v2.w, v3.x, v3.y, v3.z, v3.w};
            uint32_t hv[8], lv[8];
#pragma unroll
            for (int j = 0; j < 8; ++j) split2_pair(ff[2 * j], ff[2 * j + 1], hv[j], lv[j]);
            const int o = br * 20 + bc * 8;
            *reinterpret_cast<uint4*>(bs + B_H32 + o)     = make_uint4(hv[0], hv[1], hv[2], hv[3]);
            *reinterpret_cast<uint4*>(bs + B_H32 + o + 4) = make_uint4(hv[4], hv[5], hv[6], hv[7]);
            *reinterpret_cast<uint4*>(bs + B_L32 + o)     = make_uint4(lv[0], lv[1], lv[2], lv[3]);
            *reinterpret_cast<uint4*>(bs + B_L32 + o + 4) = make_uint4(lv[4], lv[5], lv[6], lv[7]);
        }
    };

    auto compute = [&](int bb) {
        const uint32_t base = sb + (uint32_t)bb * BSTG;
#pragma unroll
        for (int ks = 0; ks < 2; ++ks) {
            uint32_t ah[2][4], al[2][4];
#pragma unroll
            for (int mt = 0; mt < 2; ++mt) {
                uint32_t off = (uint32_t)(((wm * 32 + mt * 16 + aRow) * 40 + ks * 16 + aK8 * 8) * 2);
                LDSM4(ah[mt], base + off);
                LDSM4(al[mt], base + A_L32 * 4 + off);
            }
#pragma unroll
            for (int ntp = 0; ntp < NTW / 2; ++ntp) {
                uint32_t boff = (uint32_t)(((wn * 32 + ntp * 16 + bRow) * 40 + ks * 16 + bK8 * 8) * 2);
                uint32_t bh[4], bl[4];
                LDSM4(bh, base + B_H32 * 4 + boff);
                LDSM4(bl, base + B_L32 * 4 + boff);
                float* a00 = acc[0][2 * ntp];
                float* a01 = acc[0][2 * ntp + 1];
                float* a10 = acc[1][2 * ntp];
                float* a11 = acc[1][2 * ntp + 1];
                mma16816(a00, ah[0], bh);     mma16816(a10, ah[1], bh);
                mma16816(a01, ah[0], bh + 2); mma16816(a11, ah[1], bh + 2);
                mma16816(a00, ah[0], bl);     mma16816(a10, ah[1], bl);
                mma16816(a01, ah[0], bl + 2); mma16816(a11, ah[1], bl + 2);
                mma16816(a00, al[0], bh);     mma16816(a10, al[1], bh);
                mma16816(a01, al[0], bh + 2); mma16816(a11, al[1], bh + 2);
            }
        }
    };

    // prologue: stages 0,1 in flight; convert stage 0
    load_f(k_begin, 0);
    CP_COMMIT();
    if (S > 1) load_f(k_begin + 32, 1);
    CP_COMMIT();
    CP_WAIT1();               // stage 0 arrived
    __syncthreads();
    convert(0, 0);
    __syncthreads();

    for (int s = 0; s < S; ++s) {
        if (s + 2 < S) load_f(k_begin + (s + 2) * 32, s & 1);
        CP_COMMIT();
        compute(s & 1);
        CP_WAIT1();           // stage s+1 arrived (its group is oldest-but-one)
        if (s + 1 < S) convert((s + 1) & 1, (s + 1) & 1);
        __syncthreads();
    }

    const int g = lid >> 2, tig = lid & 3;
    float* Pbase = P + ((size_t)ksp * 128 + mtile * BM) * Ntot + ntile * BN;
#pragma unroll
    for (int mt = 0; mt < 2; ++mt) {
#pragma unroll
        for (int nt = 0; nt < NTW; ++nt) {
            int row = wm * 32 + mt * 16 + g;
            int col = wn * 32 + nt * 8 + tig * 2;
            float* d0 = Pbase + (size_t)row * Ntot + col;
            float* d1 = Pbase + (size_t)(row + 8) * Ntot + col;
            *reinterpret_cast<float2*>(d0) = make_float2(acc[mt][nt][0], acc[mt][nt][1]);
            *reinterpret_cast<float2*>(d1) = make_float2(acc[mt][nt][2], acc[mt][nt][3]);
        }
    }
}

// ===================== RoI max pool — reciprocal-division emulation (LOAD-BEARING) =====================
__global__ void roipool_kernel(const float* __restrict__ x, const float* __restrict__ rois,
                               const int* __restrict__ ridx, float* __restrict__ pooled) {
    const int r = blockIdx.x;
    const float C7 = __uint_as_float(0x3E124925u);  // fl(1/7): matches XLA reciprocal-multiply
    __shared__ int hs[7], he[7], ws_[7], we_[7];
    if (threadIdx.x < 7) {
        const int p = threadIdx.x;
        float y1 = rintf(rois[r * 4 + 0] * 0.0625f);
        float x1 = rintf(rois[r * 4 + 1] * 0.0625f);
        float y2 = rintf(rois[r * 4 + 2] * 0.0625f);
        float x2 = rintf(rois[r * 4 + 3] * 0.0625f);
        float rh = fmaxf(y2 - y1 + 1.0f, 1.0f);
        float rw = fmaxf(x2 - x1 + 1.0f, 1.0f);
        float pf = (float)p;
        hs[p]  = (int)fminf(fmaxf(y1 + floorf((pf * rh) * C7), 0.0f), 37.0f);
        he[p]  = (int)fminf(fmaxf(y1 + ceilf(((pf + 1.0f) * rh) * C7), 0.0f), 37.0f);
        ws_[p] = (int)fminf(fmaxf(x1 + floorf((pf * rw) * C7), 0.0f), 37.0f);
        we_[p] = (int)fminf(fmaxf(x1 + ceilf(((pf + 1.0f) * rw) * C7), 0.0f), 37.0f);
    }
    __syncthreads();
    const float* xb = x + (size_t)ridx[r] * N_CH * (FH * FW);
    const float NEG = __int_as_float(0xff800000);
    for (int q = threadIdx.x; q < N_CH * 49; q += blockDim.x) {
        const int c = q / 49;
        const int b = q - c * 49;
        const int ph = b / 7, pw = b - ph * 7;
        const float* xc = xb + c * (FH * FW);
        float mx = NEG;
        for (int h = hs[ph]; h < he[ph]; ++h) {
            const float* xr = xc + h * FW;
            for (int w = ws_[pw]; w < we_[pw]; ++w) mx = fmaxf(mx, xr[w]);
        }
        pooled[(size_t)r * K_FC6 + q] = (mx == NEG) ? 0.0f : mx;
    }
}

// ===================== reduce: sum split-K partials + bias + relu =====================
__global__ void reduce_kernel(const float* __restrict__ P, const float* __restrict__ bias,
                              float* __restrict__ out) {
    int idx = blockIdx.x * blockDim.x + threadIdx.x;
    if (idx >= 128 * NFC) return;
    int n = idx & (NFC - 1);
    float v = 0.0f;
#pragma unroll
    for (int s = 0; s < KSPLIT; ++s) v += P[(size_t)s * 128 * NFC + idx];
    out[idx] = fmaxf(v + bias[n], 0.0f);
}

// ===================== heads =====================
__global__ __launch_bounds__(256)
void heads_kernel(const float* __restrict__ fc7,
                  const float* __restrict__ Wsc, const float* __restrict__ bsc,
                  const float* __restrict__ Wloc, const float* __restrict__ bloc,
                  float* __restrict__ out) {
    int gw = (blockIdx.x * 256 + threadIdx.x) >> 5;
    int lane = threadIdx.x & 31;
    if (gw >= 128 * 105) return;
    int m = gw / 105, c = gw - m * 105;
    const float* wr = (c < 21) ? (Wsc + (size_t)c * NFC) : (Wloc + (size_t)(c - 21) * NFC);
    const float* arow = fc7 + (size_t)m * NFC;
    float s = 0.0f;
#pragma unroll 4
    for (int k = lane * 4; k < NFC; k += 128) {
        float4 a = *reinterpret_cast<const float4*>(arow + k);
        float4 w = *reinterpret_cast<const float4*>(wr + k);
        s += a.x * w.x + a.y * w.y + a.z * w.z + a.w * w.w;
    }
#pragma unroll
    for (int o = 16; o; o >>= 1) s += __shfl_down_sync(0xffffffffu, s, o);
    if (lane == 0) {
        if (c < 21) out[m * 21 + c] = s + bsc[c];
        else        out[128 * 21 + m * 84 + (c - 21)] = s + bloc[c - 21];
    }
}

// ===================== launch =====================
extern "C" void kernel_launch(void* const* d_in, const int* in_sizes, int n_in,
                              void* d_out, int out_size) {
    const float *x = nullptr, *rois = nullptr, *W1 = nullptr, *b1 = nullptr, *W2 = nullptr,
                *b2 = nullptr, *Wloc = nullptr, *bloc = nullptr, *Wsc = nullptr, *bsc = nullptr;
    const int* ridx = nullptr;
    for (int i = 0; i < n_in; ++i) {
        const int sz = in_sizes[i];
        const float* p = (const float*)d_in[i];
        switch (sz) {
            case 2 * N_CH * FH * FW: x = p; break;
            case N_ROIS * 4:         rois = p; break;
            case N_ROIS:             ridx = (const int*)d_in[i]; break;
            case NFC * K_FC6:        W1 = p; break;
            case NFC * NFC:          W2 = p; break;
            case 84 * NFC:           Wloc = p; break;
            case 21 * NFC:           Wsc = p; break;
            case 84:                 bloc = p; break;
            case 21:                 bsc = p; break;
            case NFC:                if (!b1) b1 = p; else b2 = p; break;
            default: break;
        }
    }
    float* out = (float*)d_out;

    float *pooled, *fc6, *fc7, *part;
    cudaGetSymbolAddress((void**)&pooled, g_pooled);
    cudaGetSymbolAddress((void**)&fc6, g_fc6);
    cudaGetSymbolAddress((void**)&fc7, g_fc7);
    cudaGetSymbolAddress((void**)&part, g_part);

    const int smem_gemm = 2 * 30720 + 2 * 24576;  // 110592
    cudaFuncSetAttribute((const void*)gemm_pipe,
                         cudaFuncAttributeMaxDynamicSharedMemorySize, smem_gemm);

    // 1. RoI max pool
    roipool_kernel<<<N_ROIS, 256>>>(x, rois, ridx, pooled);
    // 2. fc6: 32 ntiles x 2 mtiles x 4 ksplit = 256 CTAs (~1 wave @ occ 2)
    gemm_pipe<<<32 * MT * KSPLIT, 256, smem_gemm>>>(pooled, W1, part, K_FC6, K_FC6 / KSPLIT, NFC, 32);
    reduce_kernel<<<(128 * NFC + 255) / 256, 256>>>(part, b1, fc6);
    // 3. fc7
    gemm_pipe<<<32 * MT * KSPLIT, 256, smem_gemm>>>(fc6, W2, part, NFC, NFC / KSPLIT, NFC, 32);
    reduce_kernel<<<(128 * NFC + 255) / 256, 256>>>(part, b2, fc7);
    // 4. heads
    heads_kernel<<<(128 * 105 * 32 + 255) / 256, 256>>>(fc7, Wsc, bsc, Wloc, bloc, out);
}

// round 13
// speedup vs baseline: 1.2525x; 1.2525x over previous
#include <cuda_runtime.h>
#include <cuda_bf16.h>
#include <cstdint>
#include <cstddef>

// ===================== problem constants =====================
#define N_ROIS   128
#define N_CH     512
#define FH       37
#define FW       37
#define K_FC6    25088      // 512*7*7
#define NFC      4096
#define KSPLIT   8

// ===================== static scratch =====================
__device__ __align__(256) float g_pooled[N_ROIS * K_FC6];
__device__ __align__(256) float g_fc6[N_ROIS * NFC];
__device__ __align__(256) float g_fc7[N_ROIS * NFC];
__device__ __align__(256) float g_part[KSPLIT * N_ROIS * NFC];

// ===================== helpers =====================
__device__ __forceinline__ uint32_t smem_u32(const void* p) {
    uint32_t a;
    asm("{ .reg .u64 t; cvta.to.shared.u64 t, %1; cvt.u32.u64 %0, t; }" : "=r"(a) : "l"(p));
    return a;
}

__device__ __forceinline__ void split2_pair(float a, float b, uint32_t& h, uint32_t& l) {
    __nv_bfloat16 ha = __float2bfloat16_rn(a), hb = __float2bfloat16_rn(b);
    __nv_bfloat16 la = __float2bfloat16_rn(a - __bfloat162float(ha));
    __nv_bfloat16 lb = __float2bfloat16_rn(b - __bfloat162float(hb));
    h = (uint32_t)__bfloat16_as_ushort(ha) | ((uint32_t)__bfloat16_as_ushort(hb) << 16);
    l = (uint32_t)__bfloat16_as_ushort(la) | ((uint32_t)__bfloat16_as_ushort(lb) << 16);
}

__device__ __forceinline__ void mma16816(float* d, const uint32_t* a, const uint32_t* b) {
    asm volatile(
        "mma.sync.aligned.m16n8k16.row.col.f32.bf16.bf16.f32 "
        "{%0,%1,%2,%3}, {%4,%5,%6,%7}, {%8,%9}, {%0,%1,%2,%3};"
        : "+f"(d[0]), "+f"(d[1]), "+f"(d[2]), "+f"(d[3])
        : "r"(a[0]), "r"(a[1]), "r"(a[2]), "r"(a[3]), "r"(b[0]), "r"(b[1]));
}

#define LDSM4(R, ADDR) \
    asm volatile("ldmatrix.sync.aligned.m8n8.x4.shared.b16 {%0,%1,%2,%3}, [%4];" \
        : "=r"((R)[0]), "=r"((R)[1]), "=r"((R)[2]), "=r"((R)[3]) : "r"(ADDR))

// ===================== GEMM: CTA tile M128 x N128, 256 thr (8 warps, 2x4), warp tile 64x32 =====================
// Per stage (K=32): A_H|A_L|B_H|B_L planes, 80B rows, double buffered (2 x 40960 B).
// Stage schedule: ldgA(s+1) -> compute ks0 -> stsA(s+1)+ldgB(s+1) -> compute ks1 -> stsB(s+1) -> bar.
__global__ __launch_bounds__(256, 2)
void gemm_bf16x3(const float* __restrict__ A, const float* __restrict__ B,
                 float* __restrict__ P, int K, int Kchunk, int Ntot, int n_tiles)
{
    extern __shared__ uint32_t sm[];
    constexpr uint32_t STG32 = 10240;                 // b32 words per stage
    constexpr uint32_t A_L32 = 2560, B_H32 = 5120, B_L32 = 7680;
    constexpr uint32_t STG_BYTES = 40960;

    const int t = threadIdx.x;
    const int wid = t >> 5, lid = t & 31;
    const int wm = wid & 1, wn = wid >> 1;            // 2 x 4 warp grid; warp tile 64 x 32
    const int ntile = blockIdx.x % n_tiles;
    const int ksp = blockIdx.x / n_tiles;
    const int k_begin = ksp * Kchunk;
    const int S = Kchunk >> 5;

    const float* Bt = B + (size_t)(ntile * 128) * K;
    const int r2 = t >> 1, c2 = t & 1;                // loader: row 0..127, 16-float half

    const int aRow = lid & 15;
    const int aK8 = (lid >> 4) & 1;
    const int bRow = (lid & 7) | ((lid & 16) >> 1);
    const int bK8 = (lid >> 3) & 1;

    const uint32_t sb = smem_u32(sm);

    float acc[4][4][4];
#pragma unroll
    for (int i = 0; i < 4; ++i)
#pragma unroll
        for (int j = 0; j < 4; ++j)
#pragma unroll
            for (int q = 0; q < 4; ++q) acc[i][j][q] = 0.0f;

    float4 stg[4];   // staging for 16 floats (A or B in turn)

    auto ldgA = [&](int k0) {
        const float* p = A + (size_t)r2 * K + k0 + c2 * 16;
#pragma unroll
        for (int j = 0; j < 4; ++j) stg[j] = *reinterpret_cast<const float4*>(p + j * 4);
    };
    auto ldgB = [&](int k0) {
        const float* p = Bt + (size_t)r2 * K + k0 + c2 * 16;
#pragma unroll
        for (int j = 0; j < 4; ++j) stg[j] = *reinterpret_cast<const float4*>(p + j * 4);
    };

    auto sts16 = [&](uint32_t* hiBase, uint32_t* loBase) {
        float f[16] = {stg[0].x, stg[0].y, stg[0].z, stg[0].w,
                       stg[1].x, stg[1].y, stg[1].z, stg[1].w,
                       stg[2].x, stg[2].y, stg[2].z, stg[2].w,
                       stg[3].x, stg[3].y, stg[3].z, stg[3].w};
        uint32_t hv[8], lv[8];
#pragma unroll
        for (int j = 0; j < 8; ++j) split2_pair(f[2 * j], f[2 * j + 1], hv[j], lv[j]);
        const int o = r2 * 20 + c2 * 8;
        *reinterpret_cast<uint4*>(hiBase + o)     = make_uint4(hv[0], hv[1], hv[2], hv[3]);
        *reinterpret_cast<uint4*>(hiBase + o + 4) = make_uint4(hv[4], hv[5], hv[6], hv[7]);
        *reinterpret_cast<uint4*>(loBase + o)     = make_uint4(lv[0], lv[1], lv[2], lv[3]);
        *reinterpret_cast<uint4*>(loBase + o + 4) = make_uint4(lv[4], lv[5], lv[6], lv[7]);
    };
    auto stsA = [&](int buf) {
        uint32_t* s = sm + buf * STG32;
        sts16(s, s + A_L32);
    };
    auto stsB = [&](int buf) {
        uint32_t* s = sm + buf * STG32;
        sts16(s + B_H32, s + B_L32);
    };

    auto compute_ks = [&](int buf, int ks) {
        const uint32_t base = sb + (uint32_t)buf * STG_BYTES;
        uint32_t bh[2][4], bl[2][4];
#pragma unroll
        for (int ntp = 0; ntp < 2; ++ntp) {
            uint32_t boff = (uint32_t)(((wn * 32 + ntp * 16 + bRow) * 40 + ks * 16 + bK8 * 8) * 2);
            LDSM4(bh[ntp], base + B_H32 * 4 + boff);
            LDSM4(bl[ntp], base + B_L32 * 4 + boff);
        }
#pragma unroll
        for (int mt = 0; mt < 4; ++mt) {
            uint32_t aoff = (uint32_t)(((wm * 64 + mt * 16 + aRow) * 40 + ks * 16 + aK8 * 8) * 2);
            uint32_t ah[4], al[4];
            LDSM4(ah, base + aoff);
            LDSM4(al, base + A_L32 * 4 + aoff);
#pragma unroll
            for (int ntp = 0; ntp < 2; ++ntp) {
                float* d0 = acc[mt][2 * ntp];
                float* d1 = acc[mt][2 * ntp + 1];
                mma16816(d0, ah, bh[ntp]);     mma16816(d1, ah, bh[ntp] + 2);
                mma16816(d0, ah, bl[ntp]);     mma16816(d1, ah, bl[ntp] + 2);
                mma16816(d0, al, bh[ntp]);     mma16816(d1, al, bh[ntp] + 2);
            }
        }
    };

    // prologue
    ldgA(k_begin); stsA(0);
    ldgB(k_begin); stsB(0);
    __syncthreads();

    for (int s = 0; s < S; ++s) {
        const int cb = s & 1, nb = (s + 1) & 1;
        if (s + 1 < S) ldgA(k_begin + (s + 1) * 32);
        compute_ks(cb, 0);
        if (s + 1 < S) { stsA(nb); ldgB(k_begin + (s + 1) * 32); }
        compute_ks(cb, 1);
        if (s + 1 < S) stsB(nb);
        __syncthreads();
    }

    // epilogue: fp32 partials
    const int g = lid >> 2, tig = lid & 3;
    float* Pbase = P + (size_t)(ksp * 128) * Ntot + ntile * 128;
#pragma unroll
    for (int mt = 0; mt < 4; ++mt) {
#pragma unroll
        for (int nt = 0; nt < 4; ++nt) {
            int row = wm * 64 + mt * 16 + g;
            int col = wn * 32 + nt * 8 + tig * 2;
            float* d0 = Pbase + (size_t)row * Ntot + col;
            float* d1 = Pbase + (size_t)(row + 8) * Ntot + col;
            *reinterpret_cast<float2*>(d0) = make_float2(acc[mt][nt][0], acc[mt][nt][1]);
            *reinterpret_cast<float2*>(d1) = make_float2(acc[mt][nt][2], acc[mt][nt][3]);
        }
    }
}

// ===================== RoI max pool — reciprocal-division emulation (LOAD-BEARING) =====================
__global__ void roipool_kernel(const float* __restrict__ x, const float* __restrict__ rois,
                               const int* __restrict__ ridx, float* __restrict__ pooled) {
    const int r = blockIdx.x;
    const float C7 = __uint_as_float(0x3E124925u);  // fl(1/7): matches XLA reciprocal-multiply
    __shared__ int hs[7], he[7], ws_[7], we_[7];
    if (threadIdx.x < 7) {
        const int p = threadIdx.x;
        float y1 = rintf(rois[r * 4 + 0] * 0.0625f);
        float x1 = rintf(rois[r * 4 + 1] * 0.0625f);
        float y2 = rintf(rois[r * 4 + 2] * 0.0625f);
        float x2 = rintf(rois[r * 4 + 3] * 0.0625f);
        float rh = fmaxf(y2 - y1 + 1.0f, 1.0f);
        float rw = fmaxf(x2 - x1 + 1.0f, 1.0f);
        float pf = (float)p;
        hs[p]  = (int)fminf(fmaxf(y1 + floorf((pf * rh) * C7), 0.0f), 37.0f);
        he[p]  = (int)fminf(fmaxf(y1 + ceilf(((pf + 1.0f) * rh) * C7), 0.0f), 37.0f);
        ws_[p] = (int)fminf(fmaxf(x1 + floorf((pf * rw) * C7), 0.0f), 37.0f);
        we_[p] = (int)fminf(fmaxf(x1 + ceilf(((pf + 1.0f) * rw) * C7), 0.0f), 37.0f);
    }
    __syncthreads();
    const float* xb = x + (size_t)ridx[r] * N_CH * (FH * FW);
    const float NEG = __int_as_float(0xff800000);
    for (int q = threadIdx.x; q < N_CH * 49; q += blockDim.x) {
        const int c = q / 49;
        const int b = q - c * 49;
        const int ph = b / 7, pw = b - ph * 7;
        const float* xc = xb + c * (FH * FW);
        float mx = NEG;
        for (int h = hs[ph]; h < he[ph]; ++h) {
            const float* xr = xc + h * FW;
            for (int w = ws_[pw]; w < we_[pw]; ++w) mx = fmaxf(mx, xr[w]);
        }
        pooled[(size_t)r * K_FC6 + q] = (mx == NEG) ? 0.0f : mx;
    }
}

// ===================== reduce: sum split-K partials + bias + relu =====================
__global__ void reduce_kernel(const float* __restrict__ P, const float* __restrict__ bias,
                              float* __restrict__ out) {
    int idx = blockIdx.x * blockDim.x + threadIdx.x;
    if (idx >= 128 * NFC) return;
    int n = idx & (NFC - 1);
    float v = 0.0f;
#pragma unroll
    for (int s = 0; s < KSPLIT; ++s) v += P[(size_t)s * 128 * NFC + idx];
    out[idx] = fmaxf(v + bias[n], 0.0f);
}

// ===================== heads =====================
__global__ __launch_bounds__(256)
void heads_kernel(const float* __restrict__ fc7,
                  const float* __restrict__ Wsc, const float* __restrict__ bsc,
                  const float* __restrict__ Wloc, const float* __restrict__ bloc,
                  float* __restrict__ out) {
    int gw = (blockIdx.x * 256 + threadIdx.x) >> 5;
    int lane = threadIdx.x & 31;
    if (gw >= 128 * 105) return;
    int m = gw / 105, c = gw - m * 105;
    const float* wr = (c < 21) ? (Wsc + (size_t)c * NFC) : (Wloc + (size_t)(c - 21) * NFC);
    const float* arow = fc7 + (size_t)m * NFC;
    float s = 0.0f;
#pragma unroll 4
    for (int k = lane * 4; k < NFC; k += 128) {
        float4 a = *reinterpret_cast<const float4*>(arow + k);
        float4 w = *reinterpret_cast<const float4*>(wr + k);
        s += a.x * w.x + a.y * w.y + a.z * w.z + a.w * w.w;
    }
#pragma unroll
    for (int o = 16; o; o >>= 1) s += __shfl_down_sync(0xffffffffu, s, o);
    if (lane == 0) {
        if (c < 21) out[m * 21 + c] = s + bsc[c];
        else        out[128 * 21 + m * 84 + (c - 21)] = s + bloc[c - 21];
    }
}

// ===================== launch =====================
extern "C" void kernel_launch(void* const* d_in, const int* in_sizes, int n_in,
                              void* d_out, int out_size) {
    const float *x = nullptr, *rois = nullptr, *W1 = nullptr, *b1 = nullptr, *W2 = nullptr,
                *b2 = nullptr, *Wloc = nullptr, *bloc = nullptr, *Wsc = nullptr, *bsc = nullptr;
    const int* ridx = nullptr;
    for (int i = 0; i < n_in; ++i) {
        const int sz = in_sizes[i];
        const float* p = (const float*)d_in[i];
        switch (sz) {
            case 2 * N_CH * FH * FW: x = p; break;
            case N_ROIS * 4:         rois = p; break;
            case N_ROIS:             ridx = (const int*)d_in[i]; break;
            case NFC * K_FC6:        W1 = p; break;
            case NFC * NFC:          W2 = p; break;
            case 84 * NFC:           Wloc = p; break;
            case 21 * NFC:           Wsc = p; break;
            case 84:                 bloc = p; break;
            case 21:                 bsc = p; break;
            case NFC:                if (!b1) b1 = p; else b2 = p; break;
            default: break;
        }
    }
    float* out = (float*)d_out;

    float *pooled, *fc6, *fc7, *part;
    cudaGetSymbolAddress((void**)&pooled, g_pooled);
    cudaGetSymbolAddress((void**)&fc6, g_fc6);
    cudaGetSymbolAddress((void**)&fc7, g_fc7);
    cudaGetSymbolAddress((void**)&part, g_part);

    const int smem_gemm = 2 * 40960;  // 81920 B -> 2 CTAs/SM
    cudaFuncSetAttribute((const void*)gemm_bf16x3,
                         cudaFuncAttributeMaxDynamicSharedMemorySize, smem_gemm);

    // 1. RoI max pool
    roipool_kernel<<<N_ROIS, 256>>>(x, rois, ridx, pooled);
    // 2. fc6: 32 ntiles x 8 ksplit = 256 CTAs
    gemm_bf16x3<<<32 * KSPLIT, 256, smem_gemm>>>(pooled, W1, part, K_FC6, K_FC6 / KSPLIT, NFC, 32);
    reduce_kernel<<<(128 * NFC + 255) / 256, 256>>>(part, b1, fc6);
    // 3. fc7
    gemm_bf16x3<<<32 * KSPLIT, 256, smem_gemm>>>(fc6, W2, part, NFC, NFC / KSPLIT, NFC, 32);
    reduce_kernel<<<(128 * NFC + 255) / 256, 256>>>(part, b2, fc7);
    // 4. heads
    heads_kernel<<<(128 * 105 * 32 + 255) / 256, 256>>>(fc7, Wsc, bsc, Wloc, bloc, out);
}